// round 3
// baseline (speedup 1.0000x reference)
#include <cuda_runtime.h>

// SchrodingerOperator: H = Laplacian(tridiag 2,-1,-1)/dx^2 + diag(V)
// N = 8192, dx = 1/8192, inv_dx2 = 8192^2 = 67108864.
// V[i] = a0 + sum_k cos_coeff[k]*cos(2*pi*(k+1)*x_i) + sin_coeff[k]*sin(...)
// x_i = i/(N-1)  (linspace(0,1,N))
// Output: dense 8192x8192 fp32, tridiagonal, symmetric -> pure store kernel.

#define NN 8192
#define NV4 (NN / 4)          // 2048 float4 per row
#define N_MODES 12

__global__ void __launch_bounds__(256)
schrodinger_fill_kernel(const float* __restrict__ a0,
                        const float* __restrict__ cos_coeff,
                        const float* __restrict__ sin_coeff,
                        float4* __restrict__ out)
{
    // One float4 (16B) of the matrix per thread. Grid exactly covers N*N/4.
    unsigned int idx = blockIdx.x * blockDim.x + threadIdx.x;   // 0 .. 16M-1
    int row  = (int)(idx >> 11);          // idx / 2048
    int c4   = (int)(idx & 2047u);        // idx % 2048
    int col0 = c4 << 2;                   // first column of this float4

    float4 v = make_float4(0.f, 0.f, 0.f, 0.f);

    // Tridiagonal band for this row spans columns [row-1, row+1].
    // Only take the expensive path if this float4 intersects it.
    if (col0 + 3 >= row - 1 && col0 <= row + 1) {
        const float inv_dx2 = 67108864.0f;          // 8192^2
        // Compute V[row]
        const float x = (float)row * (1.0f / (float)(NN - 1));
        float Vr = a0[0];
        #pragma unroll
        for (int k = 0; k < N_MODES; k++) {
            float ph = 6.28318530717958647692f * (float)(k + 1) * x;
            float s, c;
            sincosf(ph, &s, &c);
            Vr = fmaf(cos_coeff[k], c, Vr);
            Vr = fmaf(sin_coeff[k], s, Vr);
        }
        const float diag_val = fmaf(2.0f, inv_dx2, Vr);
        const float off_val  = -inv_dx2;

        float vals[4];
        #pragma unroll
        for (int j = 0; j < 4; j++) {
            int col = col0 + j;
            float val = 0.f;
            if (col == row)                         val = diag_val;
            else if (col == row - 1 || col == row + 1) val = off_val;
            vals[j] = val;
        }
        v = make_float4(vals[0], vals[1], vals[2], vals[3]);
    }

    out[idx] = v;
}

extern "C" void kernel_launch(void* const* d_in, const int* in_sizes, int n_in,
                              void* d_out, int out_size)
{
    const float* a0        = (const float*)d_in[0];
    const float* cos_coeff = (const float*)d_in[1];
    const float* sin_coeff = (const float*)d_in[2];
    float4* out = (float4*)d_out;

    // total float4 elements = 8192*8192/4 = 16,777,216
    const unsigned int total4 = (unsigned int)NN * (unsigned int)NV4;
    const int threads = 256;
    const unsigned int blocks = total4 / threads;   // 65536, exact

    schrodinger_fill_kernel<<<blocks, threads>>>(a0, cos_coeff, sin_coeff, out);
}